// round 7
// baseline (speedup 1.0000x reference)
#include <cuda_runtime.h>
#include <cstdint>

#define LL    256   // sequence length
#define EE    64    // embed dim
#define GG    256   // 4H
#define NSEQ  2048  // B*S
#define NTHR  256
#define ROWS  32    // sequences per CTA
#define XSTRIDE 68

typedef unsigned long long u64;

__device__ __forceinline__ void fma2(u64 &d, u64 a, u64 b) {
    asm("fma.rn.f32x2 %0, %1, %2, %0;" : "+l"(d) : "l"(a), "l"(b));
}
__device__ __forceinline__ u64 pack2(float lo, float hi) {
    u64 r; asm("mov.b64 %0, {%1, %2};" : "=l"(r) : "f"(lo), "f"(hi)); return r;
}
__device__ __forceinline__ float hsum2(u64 v) {
    float lo, hi; asm("mov.b64 {%0, %1}, %2;" : "=f"(lo), "=f"(hi) : "l"(v));
    return lo + hi;
}
__device__ __forceinline__ float fsig(float x) {
    return __fdividef(1.f, 1.f + __expf(-x));
}
__device__ __forceinline__ float ftanh(float x) {
    return 2.f * __fdividef(1.f, 1.f + __expf(-2.f * x)) - 1.f;
}

// SMEM float offsets
#define OFF_WK0 0
#define OFF_WK1 8192
#define OFF_WR0 16384
#define OFF_WR1 24576
#define OFF_XS  32768                 // 2 x [32][68]
#define OFF_HS  (32768 + 4352)        // 2 x [32][68]
#define OFF_IDS (32768 + 8704)        // 8192 ints
#define SMEM_FLOATS (32768 + 8704 + 8192)

// ============================================================================
// Fused BiLSTM. 256 threads = 4 independent 64-thread groups (2 warps each).
// Group q owns rows q*8..q*8+7 end-to-end: gathers its own x, publishes its own
// h, syncs only on a named barrier -> groups drift and overlap pipes.
// Weight layout in SMEM (K-paired for f32x2), per array:
//   w[e2*256 + j*4 + g*2 + s] = W[(2*e2+s)*GG + goff*64 + j]
// ============================================================================
__global__ void __launch_bounds__(NTHR, 1)
bilstm_fused(const int* __restrict__ ids,
             const float* __restrict__ embed,
             const float* __restrict__ Wk_f, const float* __restrict__ Wr_f,
             const float* __restrict__ b_f,
             const float* __restrict__ Wk_b, const float* __restrict__ Wr_b,
             const float* __restrict__ b_b,
             float* __restrict__ out)
{
    extern __shared__ float smem[];
    float* wk0   = smem + OFF_WK0;
    float* wk1   = smem + OFF_WK1;
    float* wr0   = smem + OFF_WR0;
    float* wr1   = smem + OFF_WR1;
    float* xsbuf = smem + OFF_XS;
    float* hsbuf = smem + OFF_HS;
    int*   idss  = (int*)(smem + OFF_IDS);

    const int tid   = threadIdx.x;
    const int dir   = blockIdx.y;
    const int nbase = blockIdx.x * ROWS;

    const float* Wk = dir ? Wk_b : Wk_f;
    const float* Wr = dir ? Wr_b : Wr_f;
    const float* bb = dir ? b_b  : b_f;

    // ---- load both weight sets into K-paired layout ----
    for (int idx = tid; idx < 8192; idx += NTHR) {
        int e2  = idx >> 8;
        int rem = idx & 255;
        int jj  = rem >> 2;
        int g   = (rem >> 1) & 1;
        int s   = rem & 1;
        int e   = 2 * e2 + s;
        wk0[idx] = Wk[e * GG + g * 64 + jj];
        wk1[idx] = Wk[e * GG + (g + 2) * 64 + jj];
        wr0[idx] = Wr[e * GG + g * 64 + jj];
        wr1[idx] = Wr[e * GG + (g + 2) * 64 + jj];
    }
    // ids for this CTA's 32 rows
    for (int idx = tid; idx < ROWS * LL; idx += NTHR)
        idss[idx] = ids[(size_t)nbase * LL + idx];

    const int j     = tid & 63;          // hidden unit
    const int q     = tid >> 6;          // group 0..3
    const int r0    = q * 8;             // 8 rows per thread, group-private
    const int barid = q + 1;

    // group-private gather mapping: 8 threads per row, 8 floats each
    const int grow = r0 + (j >> 3);      // row gathered by this thread
    const int ge   = (j & 7) * 8;        // e offset

    const float bi = bb[j], bf = bb[64 + j], bg = bb[128 + j], bo = bb[192 + j];

    float c_[8], h_[8];
#pragma unroll
    for (int p = 0; p < 8; ++p) { c_[p] = 0.f; h_[p] = 0.f; }

    __syncthreads();   // weights + ids ready (only CTA-wide barrier)

    // prefetch x(step 0) into registers
    float4 xvA, xvB;
    {
        const int te0 = dir ? (LL - 1) : 0;
        int id = idss[grow * LL + te0];
        const float4* src = (const float4*)(embed + (size_t)id * EE + ge);
        xvA = src[0];
        xvB = src[1];
    }

    int buf = 0;
    for (int t = 0; t < LL; ++t) {
        const int te = dir ? (LL - 1 - t) : t;
        float* xs = xsbuf + buf * (ROWS * XSTRIDE);
        float* hs = hsbuf + buf * (ROWS * XSTRIDE);

        // ---- publish h_t and x_t (group-private rows) ----
#pragma unroll
        for (int p = 0; p < 8; ++p)
            hs[(r0 + p) * XSTRIDE + j] = h_[p];
        {
            float4* dst = (float4*)&xs[grow * XSTRIDE + ge];
            dst[0] = xvA;
            dst[1] = xvB;
        }
        asm volatile("bar.sync %0, %1;" :: "r"(barid), "r"(64) : "memory");

        // accumulators from bias
        u64 a0[8], a1[8], a2[8], a3[8];
#pragma unroll
        for (int p = 0; p < 8; ++p) {
            a0[p] = pack2(bi, 0.f);
            a1[p] = pack2(bf, 0.f);
            a2[p] = pack2(bg, 0.f);
            a3[p] = pack2(bo, 0.f);
        }

        // prefetch x(t+1) (lands under the compute below)
        {
            const int tn = (t + 1 < LL) ? (dir ? (LL - 2 - t) : (t + 1)) : te;
            int id = idss[grow * LL + tn];
            const float4* src = (const float4*)(embed + (size_t)id * EE + ge);
            xvA = src[0];
            xvB = src[1];
        }

        // ---- x @ Wk ----
#pragma unroll 2
        for (int e4 = 0; e4 < 16; ++e4) {
            const ulonglong2 wA0 = *(const ulonglong2*)(wk0 + (2 * e4) * 256 + j * 4);
            const ulonglong2 wB0 = *(const ulonglong2*)(wk1 + (2 * e4) * 256 + j * 4);
            const ulonglong2 wA1 = *(const ulonglong2*)(wk0 + (2 * e4 + 1) * 256 + j * 4);
            const ulonglong2 wB1 = *(const ulonglong2*)(wk1 + (2 * e4 + 1) * 256 + j * 4);
#pragma unroll
            for (int p = 0; p < 8; ++p) {
                ulonglong2 x4 = *(const ulonglong2*)(xs + (r0 + p) * XSTRIDE + e4 * 4);
                fma2(a0[p], x4.x, wA0.x);
                fma2(a1[p], x4.x, wA0.y);
                fma2(a2[p], x4.x, wB0.x);
                fma2(a3[p], x4.x, wB0.y);
                fma2(a0[p], x4.y, wA1.x);
                fma2(a1[p], x4.y, wA1.y);
                fma2(a2[p], x4.y, wB1.x);
                fma2(a3[p], x4.y, wB1.y);
            }
        }

        // ---- h @ Wr (h == 0 at t == 0) ----
        if (t != 0) {
#pragma unroll 2
            for (int e4 = 0; e4 < 16; ++e4) {
                const ulonglong2 wA0 = *(const ulonglong2*)(wr0 + (2 * e4) * 256 + j * 4);
                const ulonglong2 wB0 = *(const ulonglong2*)(wr1 + (2 * e4) * 256 + j * 4);
                const ulonglong2 wA1 = *(const ulonglong2*)(wr0 + (2 * e4 + 1) * 256 + j * 4);
                const ulonglong2 wB1 = *(const ulonglong2*)(wr1 + (2 * e4 + 1) * 256 + j * 4);
#pragma unroll
                for (int p = 0; p < 8; ++p) {
                    ulonglong2 h4 = *(const ulonglong2*)(hs + (r0 + p) * XSTRIDE + e4 * 4);
                    fma2(a0[p], h4.x, wA0.x);
                    fma2(a1[p], h4.x, wA0.y);
                    fma2(a2[p], h4.x, wB0.x);
                    fma2(a3[p], h4.x, wB0.y);
                    fma2(a0[p], h4.y, wA1.x);
                    fma2(a1[p], h4.y, wA1.y);
                    fma2(a2[p], h4.y, wB1.x);
                    fma2(a3[p], h4.y, wB1.y);
                }
            }
        }

        // ---- epilogue ----
#pragma unroll
        for (int p = 0; p < 8; ++p) {
            float zi = hsum2(a0[p]);
            float zf = hsum2(a1[p]);
            float zg = hsum2(a2[p]);
            float zo = hsum2(a3[p]);
            float ig  = fsig(zi);
            float fg  = fsig(zf);
            float gg2 = ftanh(zg);
            float og  = fsig(zo);
            float c = fg * c_[p] + ig * gg2;
            c_[p] = c;
            float hv = og * ftanh(c);
            h_[p] = hv;
            float* op = &out[((size_t)(nbase + r0 + p) * LL + te) * 128 + dir * 64 + j];
            asm volatile("st.global.cs.f32 [%0], %1;" :: "l"(op), "f"(hv) : "memory");
        }
        buf ^= 1;
    }
}

extern "C" void kernel_launch(void* const* d_in, const int* in_sizes, int n_in,
                              void* d_out, int out_size) {
    const int*   ids   = (const int*)  d_in[0];
    const float* embed = (const float*)d_in[1];
    const float* Wk_f  = (const float*)d_in[2];
    const float* Wr_f  = (const float*)d_in[3];
    const float* b_f   = (const float*)d_in[4];
    const float* Wk_b  = (const float*)d_in[5];
    const float* Wr_b  = (const float*)d_in[6];
    const float* b_b   = (const float*)d_in[7];
    float* out = (float*)d_out;

    static bool attr_set = false;
    if (!attr_set) {
        cudaFuncSetAttribute(bilstm_fused,
                             cudaFuncAttributeMaxDynamicSharedMemorySize,
                             SMEM_FLOATS * (int)sizeof(float));
        attr_set = true;
    }

    dim3 grid(NSEQ / ROWS, 2);   // 64 x 2 = 128 CTAs
    bilstm_fused<<<grid, NTHR, SMEM_FLOATS * sizeof(float)>>>(
        ids, embed, Wk_f, Wr_f, b_f, Wk_b, Wr_b, b_b, out);
}

// round 8
// speedup vs baseline: 1.0357x; 1.0357x over previous
#include <cuda_runtime.h>
#include <cstdint>

#define LL    256   // sequence length
#define EE    64    // embed dim
#define GG    256   // 4H
#define NSEQ  2048  // B*S

typedef unsigned long long u64;

// 1 GB scratch: pre[dir][n][t][j*4+g]  (input projection + bias, both directions)
__device__ float g_pre[(size_t)2 * NSEQ * LL * GG];

__device__ __forceinline__ void fma2(u64 &d, u64 a, u64 b) {
    asm("fma.rn.f32x2 %0, %1, %2, %0;" : "+l"(d) : "l"(a), "l"(b));
}
__device__ __forceinline__ u64 pack2(float lo, float hi) {
    u64 r; asm("mov.b64 %0, {%1, %2};" : "=l"(r) : "f"(lo), "f"(hi)); return r;
}
__device__ __forceinline__ float hsum2(u64 v) {
    float lo, hi; asm("mov.b64 {%0, %1}, %2;" : "=f"(lo), "=f"(hi) : "l"(v));
    return lo + hi;
}
__device__ __forceinline__ float tanha(float x) {
    float y; asm("tanh.approx.f32 %0, %1;" : "=f"(y) : "f"(x)); return y;
}
__device__ __forceinline__ void stcs4(float* p, float4 v) {
    asm volatile("st.global.cs.v4.f32 [%0], {%1,%2,%3,%4};"
                 :: "l"(p), "f"(v.x), "f"(v.y), "f"(v.z), "f"(v.w) : "memory");
}
__device__ __forceinline__ float4 ldcs4(const float* p) {
    float4 v;
    asm volatile("ld.global.cs.v4.f32 {%0,%1,%2,%3}, [%4];"
                 : "=f"(v.x), "=f"(v.y), "=f"(v.z), "=f"(v.w) : "l"(p));
    return v;
}

#define XSTRIDE 68

// ============================================================================
// Kernel 1: pre[dir][m][g] = embed[ids[m]] @ Wk_dir + b_dir   (m = n*LL + t)
// 512 threads = 8 INDEPENDENT 64-thread groups. Group q owns 4-row tiles,
// private double-buffered x staging, named barrier only -> groups drift.
// Weight layout in SMEM (K-paired for f32x2):
//   wk0[e2*256 + j*4 + g*2 + s] = Wk[(2*e2+s)*GG + g*64 + j]      g in {i,f}
//   wk1[e2*256 + j*4 + g*2 + s] = Wk[(2*e2+s)*GG + (g+2)*64 + j]  g in {g,o}
// ============================================================================
#define K1_NTHR 512
#define K1_TILES 8           // 4-row tiles per group
#define K1_ROWS_CTA 256      // 8 groups * 8 tiles * 4 rows
#define K1_XS_G (2 * 4 * XSTRIDE)
#define K1_SMEM_FLOATS (16384 + 8 * K1_XS_G)

__global__ void __launch_bounds__(K1_NTHR, 1)
pre_kernel(const int* __restrict__ ids,
           const float* __restrict__ embed,
           const float* __restrict__ Wk_f, const float* __restrict__ b_f,
           const float* __restrict__ Wk_b, const float* __restrict__ b_b)
{
    extern __shared__ float smem[];
    float* wk0 = smem;
    float* wk1 = smem + 8192;

    const int tid = threadIdx.x;
    const int dir = blockIdx.y;
    const float* Wk = dir ? Wk_b : Wk_f;
    const float* bb = dir ? b_b  : b_f;

    for (int idx = tid; idx < 8192; idx += K1_NTHR) {
        int e2  = idx >> 8;
        int rem = idx & 255;
        int jj  = rem >> 2;
        int g   = (rem >> 1) & 1;
        int s   = rem & 1;
        int e   = 2 * e2 + s;
        wk0[idx] = Wk[e * GG + g * 64 + jj];
        wk1[idx] = Wk[e * GG + (g + 2) * 64 + jj];
    }

    const int j     = tid & 63;
    const int q     = tid >> 6;          // group 0..7
    const int barid = q + 1;
    float* xsg = smem + 16384 + q * K1_XS_G;   // group-private 2 x [4][68]

    // gather mapping: 16 threads per row, 4 floats each
    const int grow = j >> 4;             // 0..3 local row
    const int ge   = (j & 15) * 4;       // e offset

    const float bi = bb[j], bf = bb[64 + j], bg = bb[128 + j], bo = bb[192 + j];

    const size_t m_base = (size_t)blockIdx.x * K1_ROWS_CTA + q * (K1_TILES * 4);
    const size_t dbase  = (size_t)dir * NSEQ * LL;

    __syncthreads();   // weights ready (only CTA-wide barrier)

    // prefetch tile 0
    float4 xv;
    {
        int id = ids[m_base + grow];
        xv = *(const float4*)(embed + (size_t)id * EE + ge);
    }

    int buf = 0;
    for (int tile = 0; tile < K1_TILES; ++tile) {
        float* xs = xsg + buf * (4 * XSTRIDE);
        *(float4*)&xs[grow * XSTRIDE + ge] = xv;
        asm volatile("bar.sync %0, %1;" :: "r"(barid), "r"(64) : "memory");

        // prefetch next tile (lands under compute)
        if (tile + 1 < K1_TILES) {
            int id = ids[m_base + (size_t)(tile + 1) * 4 + grow];
            xv = *(const float4*)(embed + (size_t)id * EE + ge);
        }

        u64 a0[4], a1[4], a2[4], a3[4];
#pragma unroll
        for (int p = 0; p < 4; ++p) {
            a0[p] = pack2(bi, 0.f);
            a1[p] = pack2(bf, 0.f);
            a2[p] = pack2(bg, 0.f);
            a3[p] = pack2(bo, 0.f);
        }

#pragma unroll 4
        for (int e4 = 0; e4 < 16; ++e4) {
            const ulonglong2 wA0 = *(const ulonglong2*)(wk0 + (2 * e4) * 256 + j * 4);
            const ulonglong2 wB0 = *(const ulonglong2*)(wk1 + (2 * e4) * 256 + j * 4);
            const ulonglong2 wA1 = *(const ulonglong2*)(wk0 + (2 * e4 + 1) * 256 + j * 4);
            const ulonglong2 wB1 = *(const ulonglong2*)(wk1 + (2 * e4 + 1) * 256 + j * 4);
#pragma unroll
            for (int p = 0; p < 4; ++p) {
                ulonglong2 x4 = *(const ulonglong2*)(xs + p * XSTRIDE + e4 * 4);
                fma2(a0[p], x4.x, wA0.x);
                fma2(a1[p], x4.x, wA0.y);
                fma2(a2[p], x4.x, wB0.x);
                fma2(a3[p], x4.x, wB0.y);
                fma2(a0[p], x4.y, wA1.x);
                fma2(a1[p], x4.y, wA1.y);
                fma2(a2[p], x4.y, wB1.x);
                fma2(a3[p], x4.y, wB1.y);
            }
        }

        const size_t m0 = m_base + (size_t)tile * 4;
#pragma unroll
        for (int p = 0; p < 4; ++p) {
            float4 r;
            r.x = hsum2(a0[p]);
            r.y = hsum2(a1[p]);
            r.z = hsum2(a2[p]);
            r.w = hsum2(a3[p]);
            stcs4(&g_pre[(dbase + m0 + p) * GG + j * 4], r);
        }
        buf ^= 1;
    }
}

// ============================================================================
// Kernel 2: recurrence only (h @ Wr per step). 512 threads, 4 rows/thread.
// 8 drifting 64-thread groups (named barriers), double-buffered hs,
// pre prefetched 1 step ahead; tanh.approx epilogue.
// ============================================================================
#define K2_NTHR 512
#define ROWS 32
#define K2_SMEM_FLOATS (16384 + 2 * (ROWS * XSTRIDE))

__global__ void __launch_bounds__(K2_NTHR, 1)
rec_kernel(const float* __restrict__ Wr_f,
           const float* __restrict__ Wr_b,
           float* __restrict__ out)
{
    extern __shared__ float smem[];
    float* wr0   = smem;
    float* wr1   = smem + 8192;
    float* hsbuf = smem + 16384;       // 2 x [32][68]

    const int tid   = threadIdx.x;
    const int dir   = blockIdx.y;
    const int nbase = blockIdx.x * ROWS;
    const float* Wr = dir ? Wr_b : Wr_f;

    for (int idx = tid; idx < 8192; idx += K2_NTHR) {
        int e2  = idx >> 8;
        int rem = idx & 255;
        int jj  = rem >> 2;
        int g   = (rem >> 1) & 1;
        int s   = rem & 1;
        int e   = 2 * e2 + s;
        wr0[idx] = Wr[e * GG + g * 64 + jj];
        wr1[idx] = Wr[e * GG + (g + 2) * 64 + jj];
    }

    const int j  = tid & 63;
    const int q  = tid >> 6;           // 0..7 -> group id
    const int r0 = q * 4;              // 4 rows per thread, group-private
    const int barid = q + 1;

    const float* preb = g_pre + (size_t)dir * NSEQ * LL * GG;

    float c_[4], h_[4];
    float4 pv[4];
#pragma unroll
    for (int p = 0; p < 4; ++p) { c_[p] = 0.f; h_[p] = 0.f; }

    // prefetch pre for step 0
    {
        const int te0 = dir ? (LL - 1) : 0;
#pragma unroll
        for (int p = 0; p < 4; ++p)
            pv[p] = ldcs4(&preb[((size_t)(nbase + r0 + p) * LL + te0) * GG + j * 4]);
    }

    __syncthreads();   // weights ready (only CTA-wide barrier)

    int buf = 0;
    for (int t = 0; t < LL; ++t) {
        const int te = dir ? (LL - 1 - t) : t;
        float* hs = hsbuf + buf * (ROWS * XSTRIDE);

        // publish h_t (rows r0..r0+3 — read only by this 64-thread group)
#pragma unroll
        for (int p = 0; p < 4; ++p)
            hs[(r0 + p) * XSTRIDE + j] = h_[p];
        asm volatile("bar.sync %0, %1;" :: "r"(barid), "r"(64) : "memory");

        // consume prefetched pre into accumulators
        u64 a0[4], a1[4], a2[4], a3[4];
#pragma unroll
        for (int p = 0; p < 4; ++p) {
            a0[p] = pack2(pv[p].x, 0.f);
            a1[p] = pack2(pv[p].y, 0.f);
            a2[p] = pack2(pv[p].z, 0.f);
            a3[p] = pack2(pv[p].w, 0.f);
        }

        // issue prefetch for step t+1 (lands during the compute below)
        {
            const int tn = (t + 1 < LL) ? (dir ? (LL - 2 - t) : (t + 1)) : te;
#pragma unroll
            for (int p = 0; p < 4; ++p)
                pv[p] = ldcs4(&preb[((size_t)(nbase + r0 + p) * LL + tn) * GG + j * 4]);
        }

        if (t != 0) {   // h == 0 at t==0: skip the matmul
#pragma unroll 4
            for (int e4 = 0; e4 < 16; ++e4) {
                const ulonglong2 wA0 = *(const ulonglong2*)(wr0 + (2 * e4) * 256 + j * 4);
                const ulonglong2 wB0 = *(const ulonglong2*)(wr1 + (2 * e4) * 256 + j * 4);
                const ulonglong2 wA1 = *(const ulonglong2*)(wr0 + (2 * e4 + 1) * 256 + j * 4);
                const ulonglong2 wB1 = *(const ulonglong2*)(wr1 + (2 * e4 + 1) * 256 + j * 4);
#pragma unroll
                for (int p = 0; p < 4; ++p) {
                    ulonglong2 h4 = *(const ulonglong2*)(hs + (r0 + p) * XSTRIDE + e4 * 4);
                    fma2(a0[p], h4.x, wA0.x);
                    fma2(a1[p], h4.x, wA0.y);
                    fma2(a2[p], h4.x, wB0.x);
                    fma2(a3[p], h4.x, wB0.y);
                    fma2(a0[p], h4.y, wA1.x);
                    fma2(a1[p], h4.y, wA1.y);
                    fma2(a2[p], h4.y, wB1.x);
                    fma2(a3[p], h4.y, wB1.y);
                }
            }
        }

        // epilogue: HW tanh; sigmoid(x) = 0.5*tanh(0.5x) + 0.5
#pragma unroll
        for (int p = 0; p < 4; ++p) {
            float zi = hsum2(a0[p]);
            float zf = hsum2(a1[p]);
            float zg = hsum2(a2[p]);
            float zo = hsum2(a3[p]);
            float ig  = fmaf(0.5f, tanha(0.5f * zi), 0.5f);
            float fg  = fmaf(0.5f, tanha(0.5f * zf), 0.5f);
            float gg2 = tanha(zg);
            float og  = fmaf(0.5f, tanha(0.5f * zo), 0.5f);
            float c = fg * c_[p] + ig * gg2;
            c_[p] = c;
            float hv = og * tanha(c);
            h_[p] = hv;
            float* op = &out[((size_t)(nbase + r0 + p) * LL + te) * 128 + dir * 64 + j];
            asm volatile("st.global.cs.f32 [%0], %1;" :: "l"(op), "f"(hv) : "memory");
        }
        buf ^= 1;
    }
}

extern "C" void kernel_launch(void* const* d_in, const int* in_sizes, int n_in,
                              void* d_out, int out_size) {
    const int*   ids   = (const int*)  d_in[0];
    const float* embed = (const float*)d_in[1];
    const float* Wk_f  = (const float*)d_in[2];
    const float* Wr_f  = (const float*)d_in[3];
    const float* b_f   = (const float*)d_in[4];
    const float* Wk_b  = (const float*)d_in[5];
    const float* Wr_b  = (const float*)d_in[6];
    const float* b_b   = (const float*)d_in[7];
    float* out = (float*)d_out;

    static bool attr_set = false;
    if (!attr_set) {
        cudaFuncSetAttribute(pre_kernel,
                             cudaFuncAttributeMaxDynamicSharedMemorySize,
                             K1_SMEM_FLOATS * (int)sizeof(float));
        cudaFuncSetAttribute(rec_kernel,
                             cudaFuncAttributeMaxDynamicSharedMemorySize,
                             K2_SMEM_FLOATS * (int)sizeof(float));
        attr_set = true;
    }

    dim3 grid1((NSEQ * LL) / K1_ROWS_CTA, 2);   // 2048 x 2
    pre_kernel<<<grid1, K1_NTHR, K1_SMEM_FLOATS * sizeof(float)>>>(
        ids, embed, Wk_f, b_f, Wk_b, b_b);

    dim3 grid2(NSEQ / ROWS, 2);                 // 64 x 2
    rec_kernel<<<grid2, K2_NTHR, K2_SMEM_FLOATS * sizeof(float)>>>(
        Wr_f, Wr_b, out);
}